// round 9
// baseline (speedup 1.0000x reference)
#include <cuda_runtime.h>
#include <cuda_fp16.h>
#include <cstdint>

#define D 300
#define TWO_D 600
#define NLAYERS 5
#define MAXN 200000
#define MAXG 1024
#define BN_EPS 1e-5f

// GEMM geometry: CTA tile 128(M) x 128(N), BK=16, 512 threads = 16 warps (4m x 4n),
// warp tile 32x32 = 2 mtiles(16) x 4 ntiles(8). mma.m16n8k16.f16, 3-way hi/lo split.
#define NT1 5                  // GEMM1: Nc=600 -> 5 n-tiles of 128
#define NKC1 19                // GEMM1: K=300 -> 19 k-chunks of 16
#define NT2 3                  // GEMM2: Nc=300 -> 3 n-tiles of 128
#define NKC2 38                // GEMM2: K=600
#define BTILE_WORDS 1024       // B tile: 16k x 128n f16 = 2048 halves = 1024 words

// ---------------- scratch (allocation-free: __device__ globals) ----------------
__device__ float g_h[(size_t)MAXN * D];
__device__ float g_agg[(size_t)MAXN * D];
__device__ float g_t[(size_t)MAXN * TWO_D];
__device__ float g_cnt[(size_t)MAXN * 9];
__device__ float g_gavg[(size_t)MAXG * D];
__device__ uint32_t g_w1hi[(size_t)NLAYERS * NT1 * NKC1 * BTILE_WORDS];
__device__ uint32_t g_w1lo[(size_t)NLAYERS * NT1 * NKC1 * BTILE_WORDS];
__device__ uint32_t g_w2hi[(size_t)NLAYERS * NT2 * NKC2 * BTILE_WORDS];
__device__ uint32_t g_w2lo[(size_t)NLAYERS * NT2 * NKC2 * BTILE_WORDS];

// ---------------- h0 = node_emb0[an] + node_emb1[ct]  (also zeros cnt) ----------------
__global__ void init_h_zero_kernel(const int* __restrict__ an, const int* __restrict__ ct,
                                   const float* __restrict__ e0, const float* __restrict__ e1,
                                   float* __restrict__ h, float* __restrict__ cnt, int N) {
    int idx = blockIdx.x * blockDim.x + threadIdx.x;
    if (idx < N * 9) cnt[idx] = 0.f;
    if (idx >= N * D) return;
    int n = idx / D;
    int d = idx - n * D;
    h[idx] = e0[an[n] * D + d] + e1[ct[n] * D + d];
}

// ---------------- per-dst counts of bond-type / bond-direction ----------------
__global__ void count_kernel(const int* __restrict__ bt, const int* __restrict__ bdt,
                             const int* __restrict__ dst, float* __restrict__ cnt, int E) {
    int e = blockIdx.x * blockDim.x + threadIdx.x;
    if (e >= E) return;
    int d = dst[e];
    atomicAdd(&cnt[d * 9 + bt[e]], 1.f);
    atomicAdd(&cnt[d * 9 + 6 + bdt[e]], 1.f);
}

// ---------------- agg = cnt0 @ e0[l] + cnt1 @ e1[l] ----------------
__global__ void agg_init_kernel(const float* __restrict__ cnt,
                                const float* __restrict__ e0, const float* __restrict__ e1,
                                float* __restrict__ agg, int N) {
    int idx = blockIdx.x * blockDim.x + threadIdx.x;
    if (idx >= N * 75) return;
    int n = idx / 75;
    int c = idx - n * 75;
    float4 s = make_float4(0.f, 0.f, 0.f, 0.f);
#pragma unroll
    for (int b = 0; b < 6; b++) {
        float w = cnt[n * 9 + b];
        if (w != 0.f) {
            float4 v = *(const float4*)(e0 + (size_t)b * D + c * 4);
            s.x += w * v.x; s.y += w * v.y; s.z += w * v.z; s.w += w * v.w;
        }
    }
#pragma unroll
    for (int b = 0; b < 3; b++) {
        float w = cnt[n * 9 + 6 + b];
        if (w != 0.f) {
            float4 v = *(const float4*)(e1 + (size_t)b * D + c * 4);
            s.x += w * v.x; s.y += w * v.y; s.z += w * v.z; s.w += w * v.w;
        }
    }
    *(float4*)(agg + (size_t)n * D + c * 4) = s;
}

// ---------------- scatter: agg[dst] += h[src] via vectorized red ----------------
__global__ void scatter_h_kernel(const float* __restrict__ h,
                                 const int* __restrict__ src, const int* __restrict__ dst,
                                 float* __restrict__ agg, int E) {
    int idx = blockIdx.x * blockDim.x + threadIdx.x;
    if (idx >= E * 75) return;
    int e = idx / 75;
    int c = idx - e * 75;
    float4 hv = *(const float4*)(h + (size_t)src[e] * D + c * 4);
    float* out = agg + (size_t)dst[e] * D + c * 4;
    asm volatile("red.global.add.v4.f32 [%0], {%1,%2,%3,%4};"
                 :: "l"(out), "f"(hv.x), "f"(hv.y), "f"(hv.z), "f"(hv.w) : "memory");
}

// ---------------- weight prep: fragment-major f16 hi/lo split (128-wide tiles) ----------------
// Word (nt 0..15, lane, reg): lane = g*4 + t; k = kc*16 + reg*8 + t*2 + {0,1},
// n = ntile*128 + nt*8 + g. low 16 bits = even k.
__global__ void prep_w_kernel(const float* __restrict__ W,
                              uint32_t* __restrict__ ohi, uint32_t* __restrict__ olo,
                              int K, int Nc, int NKC, int total_words) {
    int w = blockIdx.x * blockDim.x + threadIdx.x;
    if (w >= total_words) return;
    int tile = w >> 10;
    int widx = w & 1023;
    int ntile = tile / NKC, kc = tile - ntile * NKC;
    int nt = widx >> 6;
    int rem = widx & 63;
    int lane = rem >> 1, reg = rem & 1;
    int g = lane >> 2, t = lane & 3;
    int n = ntile * 128 + nt * 8 + g;
    int k0 = kc * 16 + reg * 8 + t * 2;
    float v0 = (n < Nc && k0 < K)     ? W[(size_t)k0 * Nc + n]       : 0.f;
    float v1 = (n < Nc && k0 + 1 < K) ? W[(size_t)(k0 + 1) * Nc + n] : 0.f;
    __half h0 = __float2half_rn(v0), h1 = __float2half_rn(v1);
    __half l0 = __float2half_rn(v0 - __half2float(h0));
    __half l1 = __float2half_rn(v1 - __half2float(h1));
    uint32_t ph = (uint32_t)__half_as_ushort(h0) | ((uint32_t)__half_as_ushort(h1) << 16);
    uint32_t pl = (uint32_t)__half_as_ushort(l0) | ((uint32_t)__half_as_ushort(l1) << 16);
    ohi[w] = ph;
    olo[w] = pl;
}

// ---------------- f16 split tensor-core GEMM (128x128 tile, 512 threads) ----------------
template <int MODE>
__global__ __launch_bounds__(512)
void gemm_f16_kernel(const float* __restrict__ A,
                     const uint32_t* __restrict__ Bhi, const uint32_t* __restrict__ Blo,
                     const float* __restrict__ bias,
                     const float* __restrict__ bng, const float* __restrict__ bnb,
                     const float* __restrict__ bnm, const float* __restrict__ bnv,
                     float* __restrict__ C, int M, int K, int Nc, int NKC) {
    __shared__ float As[2][2048];        // 128 rows x 16 k fp32, fragment-major
    __shared__ uint32_t Bh[2][1024];     // 16k x 128n f16 hi, fragment-major
    __shared__ uint32_t Bl[2][1024];

    const int tid = threadIdx.x;
    const int lane = tid & 31;
    const int warp = tid >> 5;           // 0..15
    const int wm = warp >> 2;            // 0..3
    const int wn = warp & 3;             // 0..3
    const int gg = lane >> 2;
    const int qq = lane & 3;
    const int rowBase = blockIdx.y * 128;
    const int colBase = blockIdx.x * 128;

    // A loader: 1 float4 chunk per thread
    const int a_row = tid >> 2;          // 0..127
    const int a_kc = (tid & 3) * 4;      // 0,4,8,12
    int a_soff;
    {
        int mt = a_row >> 4;
        int rr = a_row & 15;
        int r7 = rr & 7, rh = rr >> 3;
        int q0 = (a_kc & 7) >> 1;        // 0 or 2
        a_soff = mt * 256 + ((a_kc & 8) ? 128 : 0) + (r7 * 4 + q0) * 4 + 2 * rh;
    }
    // B loader: 1 uint4 per thread; threads 0..255 hi, 256..511 lo
    const int b_sel = tid >> 8;
    const int b_idx = tid & 255;
    const uint32_t* bthi = Bhi + (size_t)blockIdx.x * NKC * BTILE_WORDS;
    const uint32_t* btlo = Blo + (size_t)blockIdx.x * NKC * BTILE_WORDS;

    float acc[2][4][4];
#pragma unroll
    for (int mt = 0; mt < 2; mt++)
#pragma unroll
        for (int nt = 0; nt < 4; nt++)
#pragma unroll
            for (int i = 0; i < 4; i++) acc[mt][nt][i] = 0.f;

    float4 av;
    uint4 bv;

    auto ldg_tile = [&](int k0) {
        av = make_float4(0.f, 0.f, 0.f, 0.f);
        int gr = rowBase + a_row;
        if (gr < M && k0 + a_kc < K)     // K % 4 == 0: chunk all-in or all-out
            av = *(const float4*)(A + (size_t)gr * K + k0 + a_kc);
        int kc = k0 >> 4;
        const uint4* sp = (const uint4*)((b_sel ? btlo : bthi) + (size_t)kc * BTILE_WORDS);
        bv = sp[b_idx];
    };

    auto sts_tile = [&](int s) {
        float* b = &As[s][a_soff];
        *(float2*)b = make_float2(av.x, av.y);
        *(float2*)(b + 4) = make_float2(av.z, av.w);
        uint4* dp = (uint4*)(b_sel ? Bl[s] : Bh[s]);
        dp[b_idx] = bv;
    };

    ldg_tile(0);
    sts_tile(0);
    __syncthreads();
    int stage = 0;

    for (int k0 = 0; k0 < K; k0 += 16) {
        bool has_next = (k0 + 16) < K;
        if (has_next) ldg_tile(k0 + 16);

        uint32_t ah[2][4], al[2][4];
#pragma unroll
        for (int mt = 0; mt < 2; mt++) {
            const float* ap = &As[stage][(wm * 2 + mt) * 256 + lane * 4];
            float4 x = *(const float4*)ap;           // f0..f3 (k 2q..2q+1, rows g/g+8)
            float4 y = *(const float4*)(ap + 128);   // k+8
            float f[8] = {x.x, x.y, x.z, x.w, y.x, y.y, y.z, y.w};
#pragma unroll
            for (int r = 0; r < 4; r++) {
                __half2 hh = __floats2half2_rn(f[2 * r], f[2 * r + 1]);
                ah[mt][r] = *reinterpret_cast<uint32_t*>(&hh);
                float2 bk = __half22float2(hh);
                __half2 ll = __floats2half2_rn(f[2 * r] - bk.x, f[2 * r + 1] - bk.y);
                al[mt][r] = *reinterpret_cast<uint32_t*>(&ll);
            }
        }
        uint32_t bh[4][2], bl[4][2];
#pragma unroll
        for (int nt = 0; nt < 4; nt++) {
            uint2 v = *(const uint2*)(&Bh[stage][(wn * 4 + nt) * 64 + lane * 2]);
            bh[nt][0] = v.x; bh[nt][1] = v.y;
            uint2 w2 = *(const uint2*)(&Bl[stage][(wn * 4 + nt) * 64 + lane * 2]);
            bl[nt][0] = w2.x; bl[nt][1] = w2.y;
        }
#define MMA(CC, AA, BB) \
    asm volatile("mma.sync.aligned.m16n8k16.row.col.f32.f16.f16.f32 " \
                 "{%0,%1,%2,%3}, {%4,%5,%6,%7}, {%8,%9}, {%0,%1,%2,%3};" \
                 : "+f"(CC[0]), "+f"(CC[1]), "+f"(CC[2]), "+f"(CC[3]) \
                 : "r"(AA[0]), "r"(AA[1]), "r"(AA[2]), "r"(AA[3]), "r"(BB[0]), "r"(BB[1]))
#pragma unroll
        for (int mt = 0; mt < 2; mt++)
#pragma unroll
            for (int nt = 0; nt < 4; nt++) MMA(acc[mt][nt], ah[mt], bh[nt]);
#pragma unroll
        for (int mt = 0; mt < 2; mt++)
#pragma unroll
            for (int nt = 0; nt < 4; nt++) MMA(acc[mt][nt], al[mt], bh[nt]);
#pragma unroll
        for (int mt = 0; mt < 2; mt++)
#pragma unroll
            for (int nt = 0; nt < 4; nt++) MMA(acc[mt][nt], ah[mt], bl[nt]);
#undef MMA

        if (has_next) {
            sts_tile(stage ^ 1);
            __syncthreads();
            stage ^= 1;
        }
    }

    // ---- epilogue ----
#pragma unroll
    for (int nt = 0; nt < 4; nt++) {
        int col = colBase + wn * 32 + nt * 8 + qq * 2;
        if (col >= Nc) continue;         // Nc even, col even -> col+1 valid
        float bia0 = bias[col], bia1 = bias[col + 1];
        float sc0 = 1.f, sc1 = 1.f, sh0 = 0.f, sh1 = 0.f;
        if (MODE >= 2) {
            sc0 = bng[col] * rsqrtf(bnv[col] + BN_EPS);
            sc1 = bng[col + 1] * rsqrtf(bnv[col + 1] + BN_EPS);
            sh0 = bnb[col] - bnm[col] * sc0;
            sh1 = bnb[col + 1] - bnm[col + 1] * sc1;
        }
#pragma unroll
        for (int mt = 0; mt < 2; mt++) {
            float* c = acc[mt][nt];
#pragma unroll
            for (int half = 0; half < 2; half++) {
                int r = rowBase + wm * 32 + mt * 16 + gg + half * 8;
                if (r >= M) continue;
                float v0 = c[half * 2 + 0] + bia0;
                float v1 = c[half * 2 + 1] + bia1;
                if (MODE >= 2) { v0 = v0 * sc0 + sh0; v1 = v1 * sc1 + sh1; }
                if (MODE == 1 || MODE == 3) { v0 = fmaxf(v0, 0.f); v1 = fmaxf(v1, 0.f); }
                *(float2*)(C + (size_t)r * Nc + col) = make_float2(v0, v1);
            }
        }
    }
}

// ---------------- avg pool per graph ----------------
__device__ __forceinline__ int lower_bound_dev(const int* a, int n, int v) {
    int lo = 0, hi = n;
    while (lo < hi) {
        int m = (lo + hi) >> 1;
        if (a[m] < v) lo = m + 1; else hi = m;
    }
    return lo;
}

__global__ void pool_kernel(const float* __restrict__ h, const int* __restrict__ gid,
                            float* __restrict__ gavg, int N) {
    __shared__ int sh[2];
    int g = blockIdx.x;
    if (threadIdx.x == 0) sh[0] = lower_bound_dev(gid, N, g);
    if (threadIdx.x == 1) sh[1] = lower_bound_dev(gid, N, g + 1);
    __syncthreads();
    int lo = sh[0], hi = sh[1];
    int d = threadIdx.x;
    if (d >= D) return;
    float s = 0.f;
    for (int n = lo; n < hi; n++) s += h[(size_t)n * D + d];
    float cnt = (float)(hi - lo);
    gavg[(size_t)g * D + d] = s / fmaxf(cnt, 1.0f);
}

// ---------------- small fp32 GEMM for the head ----------------
__global__ __launch_bounds__(256)
void head_gemm_kernel(const float* __restrict__ A, const float* __restrict__ B,
                      const float* __restrict__ bias, float* __restrict__ C,
                      int M, int K, int Nc) {
    int row = blockIdx.y * 16 + (threadIdx.x >> 4);
    int col = blockIdx.x * 64 + (threadIdx.x & 15) * 4;
    if (row >= M || col >= Nc) return;
    float s0 = 0.f, s1 = 0.f, s2 = 0.f, s3 = 0.f;
    const float* a = A + (size_t)row * K;
    for (int k = 0; k < K; k++) {
        float av = a[k];
        const float* b = B + (size_t)k * Nc + col;
        s0 += av * b[0]; s1 += av * b[1]; s2 += av * b[2]; s3 += av * b[3];
    }
    float* out = C + (size_t)row * Nc + col;
    out[0] = s0 + bias[col];
    out[1] = s1 + bias[col + 1];
    out[2] = s2 + bias[col + 2];
    out[3] = s3 + bias[col + 3];
}

// ---------------- launch ----------------
extern "C" void kernel_launch(void* const* d_in, const int* in_sizes, int n_in,
                              void* d_out, int out_size) {
    const int* an  = (const int*)d_in[0];
    const int* ct  = (const int*)d_in[1];
    const int* bt  = (const int*)d_in[2];
    const int* bdt = (const int*)d_in[3];
    const int* src = (const int*)d_in[4];
    const int* dst = (const int*)d_in[5];
    const int* gid = (const int*)d_in[6];
    const int N = in_sizes[0];
    const int E = in_sizes[2];

    int p = 7;
    if (n_in > 7 && in_sizes[7] == 1) p = 8;
    const float* node_emb0 = (const float*)d_in[p + 0];
    const float* node_emb1 = (const float*)d_in[p + 1];
    const float* edge_emb0 = (const float*)d_in[p + 2];
    const float* edge_emb1 = (const float*)d_in[p + 3];
    const float* W1  = (const float*)d_in[p + 4];
    const float* b1  = (const float*)d_in[p + 5];
    const float* W2  = (const float*)d_in[p + 6];
    const float* b2  = (const float*)d_in[p + 7];
    const float* bng = (const float*)d_in[p + 8];
    const float* bnb = (const float*)d_in[p + 9];
    const float* bnm = (const float*)d_in[p + 10];
    const float* bnv = (const float*)d_in[p + 11];
    const float* Wd  = (const float*)d_in[p + 12];
    const float* bd  = (const float*)d_in[p + 13];
    const int G = out_size / 256;

    float *h, *agg, *t, *cnt, *gavg;
    uint32_t *w1hi, *w1lo, *w2hi, *w2lo;
    cudaGetSymbolAddress((void**)&h, g_h);
    cudaGetSymbolAddress((void**)&agg, g_agg);
    cudaGetSymbolAddress((void**)&t, g_t);
    cudaGetSymbolAddress((void**)&cnt, g_cnt);
    cudaGetSymbolAddress((void**)&gavg, g_gavg);
    cudaGetSymbolAddress((void**)&w1hi, g_w1hi);
    cudaGetSymbolAddress((void**)&w1lo, g_w1lo);
    cudaGetSymbolAddress((void**)&w2hi, g_w2hi);
    cudaGetSymbolAddress((void**)&w2lo, g_w2lo);

    const int ND = N * D;
    const int words1 = NT1 * NKC1 * BTILE_WORDS;
    const int words2 = NT2 * NKC2 * BTILE_WORDS;
    const int mtiles = (N + 127) / 128;

    init_h_zero_kernel<<<(ND + 255) / 256, 256>>>(an, ct, node_emb0, node_emb1, h, cnt, N);
    count_kernel<<<(E + 255) / 256, 256>>>(bt, bdt, dst, cnt, E);

    for (int l = 0; l < NLAYERS; l++) {
        prep_w_kernel<<<(words1 + 255) / 256, 256>>>(
            W1 + (size_t)l * D * TWO_D,
            w1hi + (size_t)l * words1, w1lo + (size_t)l * words1,
            D, TWO_D, NKC1, words1);
        agg_init_kernel<<<(N * 75 + 255) / 256, 256>>>(
            cnt, edge_emb0 + (size_t)l * 6 * D, edge_emb1 + (size_t)l * 3 * D, agg, N);
        scatter_h_kernel<<<(E * 75 + 255) / 256, 256>>>(h, src, dst, agg, E);
        gemm_f16_kernel<1><<<dim3(NT1, mtiles), 512>>>(
            agg, w1hi + (size_t)l * words1, w1lo + (size_t)l * words1,
            b1 + (size_t)l * TWO_D, nullptr, nullptr, nullptr, nullptr,
            t, N, D, TWO_D, NKC1);
        prep_w_kernel<<<(words2 + 255) / 256, 256>>>(
            W2 + (size_t)l * TWO_D * D,
            w2hi + (size_t)l * words2, w2lo + (size_t)l * words2,
            TWO_D, D, NKC2, words2);
        if (l < NLAYERS - 1) {
            gemm_f16_kernel<3><<<dim3(NT2, mtiles), 512>>>(
                t, w2hi + (size_t)l * words2, w2lo + (size_t)l * words2,
                b2 + (size_t)l * D, bng + (size_t)l * D, bnb + (size_t)l * D,
                bnm + (size_t)l * D, bnv + (size_t)l * D,
                h, N, TWO_D, D, NKC2);
        } else {
            gemm_f16_kernel<2><<<dim3(NT2, mtiles), 512>>>(
                t, w2hi + (size_t)l * words2, w2lo + (size_t)l * words2,
                b2 + (size_t)l * D, bng + (size_t)l * D, bnb + (size_t)l * D,
                bnm + (size_t)l * D, bnv + (size_t)l * D,
                h, N, TWO_D, D, NKC2);
        }
    }

    pool_kernel<<<G, 320>>>(h, gid, gavg, N);
    head_gemm_kernel<<<dim3(256 / 64, (G + 15) / 16), 256>>>(gavg, Wd, bd, (float*)d_out, G, D, 256);
}